// round 16
// baseline (speedup 1.0000x reference)
#include <cuda_runtime.h>
#include <cstdint>

#define T_FRAMES 2048
#define D_HID    1024
#define V_VOC    28
#define ROWS     8
#define NBLK_A   (T_FRAMES / ROWS)      // 256
#define NPART    (NBLK_A * 2)           // 512 partials per v
#define CHUNK    16
#define NCHUNK   (T_FRAMES / CHUNK)     // 128

#define XS_FLOATS   (ROWS * D_HID)          // 8192
#define TILE_FLOATS (V_VOC * 128)           // 3584
#define SMEM_BYTES  ((XS_FLOATS + 2 * TILE_FLOATS) * 4)   // 61440

// ---------------------------------------------------------------------------
// Device scratch (zero-initialized at module load)
// ---------------------------------------------------------------------------
__device__ float g_U[T_FRAMES * V_VOC];   // 0.5*(Uo . x[t-1]); row 0 rewritten in meta
__device__ float g_S[D_HID];              // colsum of x (atomics; self-cleaned by kSolve)
__device__ float g_CO[V_VOC];             // 0.5*(Co @ S)
__device__ float g_partMn[V_VOC * NPART];
__device__ float g_partMx[V_VOC * NPART];
__device__ int   g_m;
__device__ int   g_useSerial;
__device__ int   g_halo;                  // 8 or 16
__device__ int   g_actV[32];
__device__ float g_B28[32];
__device__ float g_W28[32 * V_VOC];
__device__ int   g_ready    = 0;          // meta-done flag (reset by last finisher)
__device__ int   g_finished = 0;

// ---------------------------------------------------------------------------
// cp.async helpers
// ---------------------------------------------------------------------------
__device__ __forceinline__ uint32_t smem_u32(const void* p) {
    return (uint32_t)__cvta_generic_to_shared(p);
}
__device__ __forceinline__ void cpAsync16(uint32_t dst, const void* src) {
    asm volatile("cp.async.cg.shared.global [%0], [%1], 16;" :: "r"(dst), "l"(src));
}
__device__ __forceinline__ void cpCommit() {
    asm volatile("cp.async.commit_group;" ::: "memory");
}
template <int N>
__device__ __forceinline__ void cpWait() {
    asm volatile("cp.async.wait_group %0;" :: "n"(N) : "memory");
}

// ---------------------------------------------------------------------------
// Kernel A: g_U[t+1][v] = 0.5*(Uo[v] . x[t]).  cp.async-pipelined; 3 blocks/SM.
// ---------------------------------------------------------------------------
__global__ void __launch_bounds__(256, 3) kA_computeU(const float* __restrict__ x,
                                                      const float* __restrict__ Uo) {
    extern __shared__ float smem[];
    float* xs = smem;                      // [ROWS][D_HID]
    float* us = smem + XS_FLOATS;          // [2][V_VOC][128]

    const int tid = threadIdx.x;
    const int t0 = blockIdx.x * ROWS;

    // prologue: G0 = { x tile, Uo tile 0 }, G1 = { Uo tile 1 }
    {
        const float* xb = x + (size_t)t0 * D_HID;
        #pragma unroll
        for (int i = 0; i < 8; i++) {
            const int e = tid + 256 * i;
            cpAsync16(smem_u32(xs + e * 4), xb + e * 4);
        }
        for (int i = tid; i < 896; i += 256) {
            const int v = i >> 5, c4 = i & 31;
            cpAsync16(smem_u32(us + v * 128 + c4 * 4),
                      Uo + (size_t)v * D_HID + c4 * 4);
        }
        cpCommit();
        for (int i = tid; i < 896; i += 256) {
            const int v = i >> 5, c4 = i & 31;
            cpAsync16(smem_u32(us + TILE_FLOATS + v * 128 + c4 * 4),
                      Uo + (size_t)v * D_HID + 128 + c4 * 4);
        }
        cpCommit();
    }

    const int warp = tid >> 5;
    const int lane = tid & 31;
    const int vg = warp & 3;                           // 7 v
    const int rh = warp >> 2;                          // 4 rows
    const int r0 = rh * 4;

    float acc[7][4];
    #pragma unroll
    for (int vi = 0; vi < 7; vi++)
        #pragma unroll
        for (int r = 0; r < 4; r++) acc[vi][r] = 0.f;

    #pragma unroll
    for (int j = 0; j < 8; j++) {
        if (j < 7) cpWait<1>(); else cpWait<0>();
        __syncthreads();

        const float* ut = us + (j & 1) * TILE_FLOATS;
        const int dd = j * 128 + lane * 4;

        float4 xr[4];
        #pragma unroll
        for (int r = 0; r < 4; r++)
            xr[r] = *reinterpret_cast<const float4*>(&xs[(r0 + r) * D_HID + dd]);

        #pragma unroll
        for (int vi = 0; vi < 7; vi++) {
            const float4 u4 = *reinterpret_cast<const float4*>(
                &ut[(vg * 7 + vi) * 128 + lane * 4]);
            #pragma unroll
            for (int r = 0; r < 4; r++) {
                float a = fmaf(u4.x, xr[r].x, acc[vi][r]);
                a = fmaf(u4.y, xr[r].y, a);
                a = fmaf(u4.z, xr[r].z, a);
                acc[vi][r] = fmaf(u4.w, xr[r].w, a);
            }
        }

        __syncthreads();
        if (j + 2 < 8) {
            float* dst = us + (j & 1) * TILE_FLOATS;
            const int joff = (j + 2) * 128;
            for (int i = tid; i < 896; i += 256) {
                const int v = i >> 5, c4 = i & 31;
                cpAsync16(smem_u32(dst + v * 128 + c4 * 4),
                          Uo + (size_t)v * D_HID + joff + c4 * 4);
            }
            cpCommit();
        }
    }

    // fused colsum (xs intact)
    #pragma unroll
    for (int i = 0; i < 4; i++) {
        const int d = tid + 256 * i;
        float s = 0.f;
        #pragma unroll
        for (int r = 0; r < ROWS; r++) s += xs[r * D_HID + d];
        atomicAdd(&g_S[d], s);
    }

    #pragma unroll
    for (int vi = 0; vi < 7; vi++) {
        const int v = vg * 7 + vi;
        float mn = 1e30f, mx = -1e30f;
        #pragma unroll
        for (int r = 0; r < 4; r++) {
            float s = acc[vi][r];
            #pragma unroll
            for (int o = 16; o; o >>= 1) s += __shfl_xor_sync(0xFFFFFFFFu, s, o);
            const int t = t0 + r0 + r + 1;
            if (lane == 0 && t < T_FRAMES) {
                const float uh = 0.5f * s;
                g_U[t * V_VOC + v] = uh;
                mn = fminf(mn, uh);
                mx = fmaxf(mx, uh);
            }
        }
        if (lane == 0) {
            g_partMn[v * NPART + blockIdx.x * 2 + rh] = mn;
            g_partMx[v * NPART + blockIdx.x * 2 + rh] = mx;
        }
    }
}

// ---------------------------------------------------------------------------
// One unified recurrence step (indexed shuffles from the active lanes)
// ---------------------------------------------------------------------------
template <int M, int NACC>
__device__ __forceinline__ float stepFn(const float* __restrict__ w,
                                        const int* __restrict__ src,
                                        float th, float bias) {
    float thc[M];
    #pragma unroll
    for (int c = 0; c < M; c++)
        thc[c] = __shfl_sync(0xFFFFFFFFu, th, src[c]);
    float a[NACC];
    a[0] = bias;
    #pragma unroll
    for (int q = 1; q < NACC; q++) a[q] = 0.f;
    #pragma unroll
    for (int c = 0; c < M; c++)
        a[c % NACC] = fmaf(w[c], thc[c], a[c % NACC]);
    float s = a[0];
    if (NACC == 2) s = a[0] + a[1];
    if (NACC == 4) s = (a[0] + a[1]) + (a[2] + a[3]);
    float nth;
    asm("tanh.approx.f32 %0, %1;" : "=f"(nth) : "f"(s));
    return nth;
}

template <int M, int NACC>
__device__ __forceinline__ void chunkBody(float* __restrict__ out) {
    const int lane = threadIdx.x;
    const int v = (lane < V_VOC) ? lane : (V_VOC - 1);
    const bool writer = (lane < V_VOC);

    const float B = g_B28[v];
    float w[M];
    int src[M];
    #pragma unroll
    for (int c = 0; c < M; c++) {
        w[c]   = g_W28[v * V_VOC + c];
        src[c] = g_actV[c];
    }

    const int halo = g_halo;
    const int t0 = blockIdx.x * CHUNK;
    const int ts = (blockIdx.x == 0) ? 0 : (t0 - halo);
    const int te = t0 + CHUNK;

    float th;
    if (blockIdx.x == 0) {
        th = -1.f;                                 // y_prev = 0 exactly
    } else {
        const float s0 = B + __ldg(&g_U[(ts - 1) * V_VOC + v]);
        asm("tanh.approx.f32 %0, %1;" : "=f"(th) : "f"(s0));
    }

    float ub[8];
    #pragma unroll
    for (int i = 0; i < 8; i++) ub[i] = __ldg(&g_U[(ts + i) * V_VOC + v]);

    for (int t = ts; t < te; t += 8) {
        #pragma unroll
        for (int i = 0; i < 8; i++) {
            const float bias = B + ub[i];
            const int tn = t + i + 8;
            if (tn < te) ub[i] = __ldg(&g_U[tn * V_VOC + v]);
            th = stepFn<M, NACC>(w, src, th, bias);
            if (writer && (t + i) >= t0)
                out[(t + i) * V_VOC + v] = fmaf(0.5f, th, 0.5f);
        }
    }
}

__device__ __forceinline__ void serialBody(float* __restrict__ out) {
    const int lane = threadIdx.x;
    const int v = (lane < V_VOC) ? lane : (V_VOC - 1);
    const bool writer = (lane < V_VOC);

    const float B = g_B28[v];
    float w[V_VOC];
    int src[V_VOC];
    #pragma unroll
    for (int c = 0; c < V_VOC; c++) {
        w[c]   = g_W28[v * V_VOC + c];
        src[c] = g_actV[c];
    }

    float ub[8];
    #pragma unroll
    for (int i = 0; i < 8; i++) ub[i] = g_U[i * V_VOC + v];

    float th = -1.0f;
    for (int t = 0; t < T_FRAMES; t += 8) {
        #pragma unroll
        for (int i = 0; i < 8; i++) {
            const float bias = B + ub[i];
            const int tn = t + i + 8;
            if (tn < T_FRAMES) ub[i] = __ldg(&g_U[tn * V_VOC + v]);
            th = stepFn<V_VOC, 4>(w, src, th, bias);
            if (writer) out[(t + i) * V_VOC + v] = fmaf(0.5f, th, 0.5f);
        }
    }
}

// ---------------------------------------------------------------------------
// Fused kernel: block 0 (28 warps) runs meta (CO + min/max + classify +
// tables + g_S self-clean), publishes g_ready; all blocks' warp 0 then run
// the chunked solver. 128 blocks <= 148 SMs -> all resident, spin is safe.
// Last finisher resets flags for the next graph replay.
// ---------------------------------------------------------------------------
__global__ void __launch_bounds__(896) kSolve(const float* __restrict__ Co,
                                              const float* __restrict__ Wo,
                                              float* __restrict__ out) {
    const int warp = threadIdx.x >> 5;
    const int lane = threadIdx.x & 31;

    if (blockIdx.x == 0) {
        {   // CO[v] = 0.5 * (Co[v] . S)   (warp == v)
            float s = 0.f;
            #pragma unroll 8
            for (int j = 0; j < 32; j++) {
                const int d = j * 32 + lane;
                s = fmaf(__ldg(&Co[warp * D_HID + d]), g_S[d], s);
            }
            #pragma unroll
            for (int o = 16; o; o >>= 1) s += __shfl_xor_sync(0xFFFFFFFFu, s, o);
            if (lane == 0) g_CO[warp] = 0.5f * s;
        }
        {   // per-v min/max reduce over NPART partials (include t=0 value 0)
            float mn = 0.f, mx = 0.f;
            #pragma unroll
            for (int i = 0; i < NPART / 32; i++) {
                mn = fminf(mn, g_partMn[warp * NPART + lane + 32 * i]);
                mx = fmaxf(mx, g_partMx[warp * NPART + lane + 32 * i]);
            }
            #pragma unroll
            for (int o = 16; o; o >>= 1) {
                mn = fminf(mn, __shfl_xor_sync(0xFFFFFFFFu, mn, o));
                mx = fmaxf(mx, __shfl_xor_sync(0xFFFFFFFFu, mx, o));
            }
            if (lane == 0) { g_partMn[warp * NPART] = mn; g_partMx[warp * NPART] = mx; }
        }
        __syncthreads();
        // self-clean g_S for the next replay (all readers are done)
        for (int i = threadIdx.x; i < D_HID; i += 896) g_S[i] = 0.f;

        if (warp == 0) {
            // classification + tables. All shuffles uniform.
            const bool valid = lane < V_VOC;
            const int vIdx = valid ? lane : 0;

            float w[V_VOC];
            float rowNeg = 0.f, rowPos = 0.f;
            #pragma unroll
            for (int k = 0; k < V_VOC; k++) {
                w[k] = Wo[vIdx * V_VOC + k];
                rowNeg += fminf(w[k], 0.f);
                rowPos += fmaxf(w[k], 0.f);
            }
            const float coh  = g_CO[vIdx];
            const float sMin = coh + g_partMn[vIdx * NPART] + 0.5f * rowNeg;
            const float sMax = coh + g_partMx[vIdx * NPART] + 0.5f * rowPos;

            int cls = 2;
            if (sMin > 7.f)  cls = 1;
            if (sMax < -7.f) cls = 0;
            if (!valid)      cls = 0;

            const unsigned amask = __ballot_sync(0xFFFFFFFFu, cls == 2) & 0x0FFFFFFFu;
            const int m = __popc(amask);
            if (lane == 0) g_m = m;

            int clsA[V_VOC];
            #pragma unroll
            for (int k = 0; k < V_VOC; k++)
                clsA[k] = __shfl_sync(0xFFFFFFFFu, cls, k);

            float s1 = 0.f;
            #pragma unroll
            for (int k = 0; k < V_VOC; k++)
                if (clsA[k] == 1) s1 += w[k];

            int act[V_VOC];
            int cnt = 0;
            #pragma unroll
            for (int k = 0; k < V_VOC; k++)
                if ((amask >> k) & 1u) act[cnt++] = k;

            float sa = 0.f, qrow = 0.f;
            #pragma unroll
            for (int j = 0; j < V_VOC; j++) {
                float wj = 0.f;
                if (j < m) wj = w[act[j]];
                g_W28[lane * V_VOC + j] = 0.25f * wj;
                sa += wj;
                qrow += 0.25f * fabsf(wj);
            }
            g_B28[lane] = coh + 0.5f * s1 + 0.25f * sa;
            g_actV[lane] = (lane < m) ? act[lane] : 0;

            if (cls != 2) qrow = 0.f;
            #pragma unroll
            for (int o = 16; o; o >>= 1)
                qrow = fmaxf(qrow, __shfl_xor_sync(0xFFFFFFFFu, qrow, o));
            if (lane == 0) {
                g_useSerial = (m > 16 || qrow > 0.40f) ? 1 : 0;
                const float q = fmaxf(qrow, 1e-4f);
                g_halo = (9.f * __logf(q) < -16.2f) ? 8 : 16;
            }
            if (valid) g_U[lane] = -0.5f * s1;   // t=0 exactness: Uh0 = -0.5*s1

            __threadfence();
            if (lane == 0) atomicExch(&g_ready, 1);
        } else {
            return;                                  // meta helper warps done
        }
    } else {
        if (threadIdx.x >= 32) return;               // only warp 0 solves
        if (lane == 0) {
            while (atomicAdd(&g_ready, 0) == 0) __nanosleep(64);
        }
        __syncwarp();
        __threadfence();
    }

    // ---- solver: warp 0 of every block ----
    if (g_useSerial) {
        if (blockIdx.x == 0) serialBody(out);
    } else {
        const int m = g_m;
        if      (m <= 4) chunkBody<4, 2>(out);
        else if (m <= 8) chunkBody<8, 4>(out);
        else             chunkBody<16, 4>(out);
    }

    // finish protocol: last block resets flags for the next replay
    if (lane == 0) {
        __threadfence();
        const int f = atomicAdd(&g_finished, 1);
        if (f == NCHUNK - 1) { g_finished = 0; g_ready = 0; }
    }
}

// ---------------------------------------------------------------------------
extern "C" void kernel_launch(void* const* d_in, const int* in_sizes, int n_in,
                              void* d_out, int out_size) {
    const float* x  = (const float*)d_in[0];   // (1, 2048, 1024)
    // d_in[1..3] = Wa, Ua, Va : mathematically dead (softmax over size-1 axis)
    const float* Wo = (const float*)d_in[4];   // (28, 28)
    const float* Uo = (const float*)d_in[5];   // (28, 1024)
    const float* Co = (const float*)d_in[6];   // (28, 1024)
    float* out = (float*)d_out;                // (1, 2048, 28)

    cudaFuncSetAttribute(kA_computeU,
                         cudaFuncAttributeMaxDynamicSharedMemorySize,
                         SMEM_BYTES);

    kA_computeU<<<NBLK_A, 256, SMEM_BYTES>>>(x, Uo);
    kSolve<<<NCHUNK, 896>>>(Co, Wo, out);
}

// round 17
// speedup vs baseline: 1.0440x; 1.0440x over previous
#include <cuda_runtime.h>
#include <cstdint>

#define T_FRAMES 2048
#define D_HID    1024
#define V_VOC    28
#define ROWS     8
#define NBLK_A   (T_FRAMES / ROWS)      // 256
#define NPART    (NBLK_A * 2)           // 512 partials per v
#define CHUNK    16
#define NCHUNK   (T_FRAMES / CHUNK)     // 128

#define XS_FLOATS   (ROWS * D_HID)          // 8192
#define TILE_FLOATS (V_VOC * 128)           // 3584
#define SMEM_BYTES  ((XS_FLOATS + 2 * TILE_FLOATS) * 4)   // 61440

// ---------------------------------------------------------------------------
// Device scratch (zero-initialized at module load; g_S self-cleaned by kMeta)
// ---------------------------------------------------------------------------
__device__ float g_U[T_FRAMES * V_VOC];   // 0.5*(Uo . x[t-1]); row 0 rewritten by kMeta
__device__ float g_S[D_HID];              // colsum of x (atomics)
__device__ float g_CO[V_VOC];             // 0.5*(Co @ S)
__device__ float g_partMn[V_VOC * NPART];
__device__ float g_partMx[V_VOC * NPART];
__device__ int   g_m;
__device__ int   g_useSerial;
__device__ int   g_halo;                  // 8 or 16
__device__ int   g_actV[32];
__device__ float g_B28[32];
__device__ float g_W28[32 * V_VOC];

// ---------------------------------------------------------------------------
// cp.async helpers
// ---------------------------------------------------------------------------
__device__ __forceinline__ uint32_t smem_u32(const void* p) {
    return (uint32_t)__cvta_generic_to_shared(p);
}
__device__ __forceinline__ void cpAsync16(uint32_t dst, const void* src) {
    asm volatile("cp.async.cg.shared.global [%0], [%1], 16;" :: "r"(dst), "l"(src));
}
__device__ __forceinline__ void cpCommit() {
    asm volatile("cp.async.commit_group;" ::: "memory");
}
template <int N>
__device__ __forceinline__ void cpWait() {
    asm volatile("cp.async.wait_group %0;" :: "n"(N) : "memory");
}

// ---------------------------------------------------------------------------
// Kernel A (round-15, measured 12.2us): cp.async-pipelined U GEMM + colsum.
// ---------------------------------------------------------------------------
__global__ void __launch_bounds__(256) kA_computeU(const float* __restrict__ x,
                                                   const float* __restrict__ Uo) {
    extern __shared__ float smem[];
    float* xs = smem;                      // [ROWS][D_HID]
    float* us = smem + XS_FLOATS;          // [2][V_VOC][128]

    const int tid = threadIdx.x;
    const int t0 = blockIdx.x * ROWS;

    // prologue: G0 = { x tile, Uo tile 0 }, G1 = { Uo tile 1 }
    {
        const float* xb = x + (size_t)t0 * D_HID;
        #pragma unroll
        for (int i = 0; i < 8; i++) {
            const int e = tid + 256 * i;
            cpAsync16(smem_u32(xs + e * 4), xb + e * 4);
        }
        for (int i = tid; i < 896; i += 256) {
            const int v = i >> 5, c4 = i & 31;
            cpAsync16(smem_u32(us + v * 128 + c4 * 4),
                      Uo + (size_t)v * D_HID + c4 * 4);
        }
        cpCommit();
        for (int i = tid; i < 896; i += 256) {
            const int v = i >> 5, c4 = i & 31;
            cpAsync16(smem_u32(us + TILE_FLOATS + v * 128 + c4 * 4),
                      Uo + (size_t)v * D_HID + 128 + c4 * 4);
        }
        cpCommit();
    }

    const int warp = tid >> 5;
    const int lane = tid & 31;
    const int vg = warp & 3;                           // 7 v
    const int rh = warp >> 2;                          // 4 rows
    const int r0 = rh * 4;

    float acc[7][4];
    #pragma unroll
    for (int vi = 0; vi < 7; vi++)
        #pragma unroll
        for (int r = 0; r < 4; r++) acc[vi][r] = 0.f;

    #pragma unroll
    for (int j = 0; j < 8; j++) {
        if (j < 7) cpWait<1>(); else cpWait<0>();
        __syncthreads();

        const float* ut = us + (j & 1) * TILE_FLOATS;
        const int dd = j * 128 + lane * 4;

        float4 xr[4];
        #pragma unroll
        for (int r = 0; r < 4; r++)
            xr[r] = *reinterpret_cast<const float4*>(&xs[(r0 + r) * D_HID + dd]);

        #pragma unroll
        for (int vi = 0; vi < 7; vi++) {
            const float4 u4 = *reinterpret_cast<const float4*>(
                &ut[(vg * 7 + vi) * 128 + lane * 4]);
            #pragma unroll
            for (int r = 0; r < 4; r++) {
                float a = fmaf(u4.x, xr[r].x, acc[vi][r]);
                a = fmaf(u4.y, xr[r].y, a);
                a = fmaf(u4.z, xr[r].z, a);
                acc[vi][r] = fmaf(u4.w, xr[r].w, a);
            }
        }

        __syncthreads();
        if (j + 2 < 8) {
            float* dst = us + (j & 1) * TILE_FLOATS;
            const int joff = (j + 2) * 128;
            for (int i = tid; i < 896; i += 256) {
                const int v = i >> 5, c4 = i & 31;
                cpAsync16(smem_u32(dst + v * 128 + c4 * 4),
                          Uo + (size_t)v * D_HID + joff + c4 * 4);
            }
            cpCommit();
        }
    }

    // fused colsum (xs intact)
    #pragma unroll
    for (int i = 0; i < 4; i++) {
        const int d = tid + 256 * i;
        float s = 0.f;
        #pragma unroll
        for (int r = 0; r < ROWS; r++) s += xs[r * D_HID + d];
        atomicAdd(&g_S[d], s);
    }

    #pragma unroll
    for (int vi = 0; vi < 7; vi++) {
        const int v = vg * 7 + vi;
        float mn = 1e30f, mx = -1e30f;
        #pragma unroll
        for (int r = 0; r < 4; r++) {
            float s = acc[vi][r];
            #pragma unroll
            for (int o = 16; o; o >>= 1) s += __shfl_xor_sync(0xFFFFFFFFu, s, o);
            const int t = t0 + r0 + r + 1;
            if (lane == 0 && t < T_FRAMES) {
                const float uh = 0.5f * s;
                g_U[t * V_VOC + v] = uh;
                mn = fminf(mn, uh);
                mx = fmaxf(mx, uh);
            }
        }
        if (lane == 0) {
            g_partMn[v * NPART + blockIdx.x * 2 + rh] = mn;
            g_partMx[v * NPART + blockIdx.x * 2 + rh] = mx;
        }
    }
}

// ---------------------------------------------------------------------------
// Kernel Meta (round-12): CO + min/max reduce + classify + tables.
// Self-cleans g_S after reading (replaces the memset graph node).
// ---------------------------------------------------------------------------
__global__ void __launch_bounds__(896) kMeta(const float* __restrict__ Co,
                                             const float* __restrict__ Wo) {
    const int warp = threadIdx.x >> 5;   // == v
    const int lane = threadIdx.x & 31;

    {   // CO[v] = 0.5 * (Co[v] . S)
        float s = 0.f;
        #pragma unroll 8
        for (int j = 0; j < 32; j++) {
            const int d = j * 32 + lane;
            s = fmaf(__ldg(&Co[warp * D_HID + d]), g_S[d], s);
        }
        #pragma unroll
        for (int o = 16; o; o >>= 1) s += __shfl_xor_sync(0xFFFFFFFFu, s, o);
        if (lane == 0) g_CO[warp] = 0.5f * s;
    }
    {   // per-v min/max reduce over NPART partials (include t=0 value 0)
        float mn = 0.f, mx = 0.f;
        #pragma unroll
        for (int i = 0; i < NPART / 32; i++) {
            mn = fminf(mn, g_partMn[warp * NPART + lane + 32 * i]);
            mx = fmaxf(mx, g_partMx[warp * NPART + lane + 32 * i]);
        }
        #pragma unroll
        for (int o = 16; o; o >>= 1) {
            mn = fminf(mn, __shfl_xor_sync(0xFFFFFFFFu, mn, o));
            mx = fmaxf(mx, __shfl_xor_sync(0xFFFFFFFFu, mx, o));
        }
        if (lane == 0) { g_partMn[warp * NPART] = mn; g_partMx[warp * NPART] = mx; }
    }
    __syncthreads();

    // self-clean g_S for the next graph replay (CO phase already consumed it)
    for (int i = threadIdx.x; i < D_HID; i += 896) g_S[i] = 0.f;

    if (warp != 0) return;

    // warp 0: classification + tables. All shuffles uniform.
    const bool valid = lane < V_VOC;
    const int vIdx = valid ? lane : 0;

    float w[V_VOC];
    float rowNeg = 0.f, rowPos = 0.f;
    #pragma unroll
    for (int k = 0; k < V_VOC; k++) {
        w[k] = Wo[vIdx * V_VOC + k];
        rowNeg += fminf(w[k], 0.f);
        rowPos += fmaxf(w[k], 0.f);
    }
    const float coh  = g_CO[vIdx];
    const float sMin = coh + g_partMn[vIdx * NPART] + 0.5f * rowNeg;
    const float sMax = coh + g_partMx[vIdx * NPART] + 0.5f * rowPos;

    int cls = 2;
    if (sMin > 7.f)  cls = 1;
    if (sMax < -7.f) cls = 0;
    if (!valid)      cls = 0;

    const unsigned amask = __ballot_sync(0xFFFFFFFFu, cls == 2) & 0x0FFFFFFFu;
    const int m = __popc(amask);
    if (lane == 0) g_m = m;

    int clsA[V_VOC];
    #pragma unroll
    for (int k = 0; k < V_VOC; k++)
        clsA[k] = __shfl_sync(0xFFFFFFFFu, cls, k);

    float s1 = 0.f;
    #pragma unroll
    for (int k = 0; k < V_VOC; k++)
        if (clsA[k] == 1) s1 += w[k];

    int act[V_VOC];
    int cnt = 0;
    #pragma unroll
    for (int k = 0; k < V_VOC; k++)
        if ((amask >> k) & 1u) act[cnt++] = k;

    float sa = 0.f, qrow = 0.f;
    #pragma unroll
    for (int j = 0; j < V_VOC; j++) {
        float wj = 0.f;
        if (j < m) wj = w[act[j]];
        g_W28[lane * V_VOC + j] = 0.25f * wj;
        sa += wj;
        qrow += 0.25f * fabsf(wj);
    }
    g_B28[lane] = coh + 0.5f * s1 + 0.25f * sa;
    g_actV[lane] = (lane < m) ? act[lane] : 0;

    if (cls != 2) qrow = 0.f;
    #pragma unroll
    for (int o = 16; o; o >>= 1)
        qrow = fmaxf(qrow, __shfl_xor_sync(0xFFFFFFFFu, qrow, o));
    if (lane == 0) {
        g_useSerial = (m > 16 || qrow > 0.40f) ? 1 : 0;
        const float q = fmaxf(qrow, 1e-4f);
        g_halo = (9.f * __logf(q) < -16.2f) ? 8 : 16;
    }

    // t=0 exactness under folded-bias form: Uh0 = -0.5*s1
    if (valid) g_U[lane] = -0.5f * s1;
}

// ---------------------------------------------------------------------------
// One unified recurrence step (indexed shuffles from the active lanes)
// ---------------------------------------------------------------------------
template <int M, int NACC>
__device__ __forceinline__ float stepFn(const float* __restrict__ w,
                                        const int* __restrict__ src,
                                        float th, float bias) {
    float thc[M];
    #pragma unroll
    for (int c = 0; c < M; c++)
        thc[c] = __shfl_sync(0xFFFFFFFFu, th, src[c]);
    float a[NACC];
    a[0] = bias;
    #pragma unroll
    for (int q = 1; q < NACC; q++) a[q] = 0.f;
    #pragma unroll
    for (int c = 0; c < M; c++)
        a[c % NACC] = fmaf(w[c], thc[c], a[c % NACC]);
    float s = a[0];
    if (NACC == 2) s = a[0] + a[1];
    if (NACC == 4) s = (a[0] + a[1]) + (a[2] + a[3]);
    float nth;
    asm("tanh.approx.f32 %0, %1;" : "=f"(nth) : "f"(s));
    return nth;
}

template <int M, int NACC>
__device__ __forceinline__ void chunkBody(float* __restrict__ out) {
    const int lane = threadIdx.x;
    const int v = (lane < V_VOC) ? lane : (V_VOC - 1);
    const bool writer = (lane < V_VOC);

    const float B = g_B28[v];
    float w[M];
    int src[M];
    #pragma unroll
    for (int c = 0; c < M; c++) {
        w[c]   = g_W28[v * V_VOC + c];
        src[c] = g_actV[c];
    }

    const int halo = g_halo;
    const int t0 = blockIdx.x * CHUNK;
    const int ts = (blockIdx.x == 0) ? 0 : (t0 - halo);
    const int te = t0 + CHUNK;

    float th;
    if (blockIdx.x == 0) {
        th = -1.f;                                 // y_prev = 0 exactly
    } else {
        const float s0 = B + __ldg(&g_U[(ts - 1) * V_VOC + v]);
        asm("tanh.approx.f32 %0, %1;" : "=f"(th) : "f"(s0));
    }

    float ub[8];
    #pragma unroll
    for (int i = 0; i < 8; i++) ub[i] = __ldg(&g_U[(ts + i) * V_VOC + v]);

    for (int t = ts; t < te; t += 8) {
        #pragma unroll
        for (int i = 0; i < 8; i++) {
            const float bias = B + ub[i];
            const int tn = t + i + 8;
            if (tn < te) ub[i] = __ldg(&g_U[tn * V_VOC + v]);
            th = stepFn<M, NACC>(w, src, th, bias);
            if (writer && (t + i) >= t0)
                out[(t + i) * V_VOC + v] = fmaf(0.5f, th, 0.5f);
        }
    }
}

__device__ __forceinline__ void serialBody(float* __restrict__ out) {
    const int lane = threadIdx.x;
    const int v = (lane < V_VOC) ? lane : (V_VOC - 1);
    const bool writer = (lane < V_VOC);

    const float B = g_B28[v];
    float w[V_VOC];
    int src[V_VOC];
    #pragma unroll
    for (int c = 0; c < V_VOC; c++) {
        w[c]   = g_W28[v * V_VOC + c];
        src[c] = g_actV[c];
    }

    float ub[8];
    #pragma unroll
    for (int i = 0; i < 8; i++) ub[i] = g_U[i * V_VOC + v];

    float th = -1.0f;
    for (int t = 0; t < T_FRAMES; t += 8) {
        #pragma unroll
        for (int i = 0; i < 8; i++) {
            const float bias = B + ub[i];
            const int tn = t + i + 8;
            if (tn < T_FRAMES) ub[i] = __ldg(&g_U[tn * V_VOC + v]);
            th = stepFn<V_VOC, 4>(w, src, th, bias);
            if (writer) out[(t + i) * V_VOC + v] = fmaf(0.5f, th, 0.5f);
        }
    }
}

__global__ void __launch_bounds__(32) kD_solve(float* __restrict__ out) {
    if (g_useSerial) {
        if (blockIdx.x != 0) return;
        serialBody(out);
        return;
    }
    const int m = g_m;
    if      (m <= 4) chunkBody<4, 2>(out);
    else if (m <= 8) chunkBody<8, 4>(out);
    else             chunkBody<16, 4>(out);
}

// ---------------------------------------------------------------------------
extern "C" void kernel_launch(void* const* d_in, const int* in_sizes, int n_in,
                              void* d_out, int out_size) {
    const float* x  = (const float*)d_in[0];   // (1, 2048, 1024)
    // d_in[1..3] = Wa, Ua, Va : mathematically dead (softmax over size-1 axis)
    const float* Wo = (const float*)d_in[4];   // (28, 28)
    const float* Uo = (const float*)d_in[5];   // (28, 1024)
    const float* Co = (const float*)d_in[6];   // (28, 1024)
    float* out = (float*)d_out;                // (1, 2048, 28)

    cudaFuncSetAttribute(kA_computeU,
                         cudaFuncAttributeMaxDynamicSharedMemorySize,
                         SMEM_BYTES);

    kA_computeU<<<NBLK_A, 256, SMEM_BYTES>>>(x, Uo);
    kMeta<<<1, 896>>>(Co, Wo);
    kD_solve<<<NCHUNK, 32>>>(out);
}